// round 4
// baseline (speedup 1.0000x reference)
#include <cuda_runtime.h>
#include <cuda_fp16.h>
#include <cstdint>
#include <cstddef>

// Problem dims
#define BB 64
#define NI 1024
#define DI 16
#define NJ 32
#define DJ 32
#define IPW 16                      // i's per warp in routing passes
#define PASS_WARPS 4                // warps per pass block
#define PASS_GRID_Y (NI / (PASS_WARPS * IPW))   // 16

// Scratch (device globals; no dynamic allocation allowed)
__device__ __align__(16) __half g_hat[(size_t)BB * NI * NJ * DJ];  // 128 MB
__device__ __align__(16) float  g_acc[BB * NJ * DJ];               // pre-squash accumulator
__device__ __align__(16) float  g_outprev[BB * NJ * DJ];           // logit operand (out0, then out0+out1)

// ---------- packed f32x2 helpers ----------
__device__ __forceinline__ unsigned long long pack2f(float x, float y) {
    unsigned long long r;
    asm("mov.b64 %0, {%1, %2};" : "=l"(r) : "f"(x), "f"(y));
    return r;
}
__device__ __forceinline__ unsigned long long ffma2(unsigned long long a, unsigned long long b,
                                                    unsigned long long c) {
    unsigned long long d;
    asm("fma.rn.f32x2 %0, %1, %2, %3;" : "=l"(d) : "l"(a), "l"(b), "l"(c));
    return d;
}
__device__ __forceinline__ float2 unpack2f(unsigned long long v) {
    float lo, hi;
    asm("mov.b64 {%0, %1}, %2;" : "=f"(lo), "=f"(hi) : "l"(v));
    return make_float2(lo, hi);
}
__device__ __forceinline__ float2 h2f2(uint32_t u) {
    __half2 h = *reinterpret_cast<__half2*>(&u);
    return __half22float2(h);
}

// ============================================================================
// K1: hat[b,i,j,m] = sum_n W[i,j,n,m] * x[b,i,n], stored fp16.
// grid = NI blocks (one i each), 256 threads; thread t owns jm = 4t..4t+3.
// x for ALL 64 b's preloaded into smem once (splatted float2 -> direct ffma2
// operand), so the b-loop has zero barriers. Blocks 0..255 zero g_acc.
// ============================================================================
__global__ __launch_bounds__(256) void k_hat(const float* __restrict__ inp,
                                             const float* __restrict__ W) {
    const int i = blockIdx.x;
    const int t = threadIdx.x;

    if (i < 256) g_acc[i * 256 + t] = 0.f;   // 256*256 = 65536 = BB*NJ*DJ

    const int j  = t >> 3;
    const int m0 = (4 * t) & 31;

    const float4* Wp = reinterpret_cast<const float4*>(
        W + ((size_t)i * NJ + j) * (DI * DJ) + m0);
    unsigned long long w01[16], w23[16];
#pragma unroll
    for (int n = 0; n < 16; n++) {
        float4 w = Wp[n * (DJ / 4)];
        w01[n] = pack2f(w.x, w.y);
        w23[n] = pack2f(w.z, w.w);
    }

    // Splatted x table: s_x2[b][n] = (x, x) as a 64-bit value.
    __shared__ __align__(16) float2 s_x2[BB][DI];
    {
        const int b  = t >> 2;               // 0..63
        const int q  = t & 3;                // 0..3 -> n = 4q..4q+3
        float4 v = reinterpret_cast<const float4*>(inp)[((size_t)b * NI + i) * 4 + q];
        s_x2[b][4 * q + 0] = make_float2(v.x, v.x);
        s_x2[b][4 * q + 1] = make_float2(v.y, v.y);
        s_x2[b][4 * q + 2] = make_float2(v.z, v.z);
        s_x2[b][4 * q + 3] = make_float2(v.w, v.w);
    }
    __syncthreads();

#pragma unroll 2
    for (int b = 0; b < BB; b++) {
        unsigned long long a01 = 0ULL, a23 = 0ULL;
#pragma unroll
        for (int n = 0; n < 16; n++) {
            unsigned long long xx =
                *reinterpret_cast<const unsigned long long*>(&s_x2[b][n]);
            a01 = ffma2(xx, w01[n], a01);
            a23 = ffma2(xx, w23[n], a23);
        }
        float2 f01 = unpack2f(a01);
        float2 f23 = unpack2f(a23);
        __half2 h0 = __floats2half2_rn(f01.x, f01.y);
        __half2 h1 = __floats2half2_rn(f23.x, f23.y);
        uint2 st;
        st.x = reinterpret_cast<uint32_t&>(h0);
        st.y = reinterpret_cast<uint32_t&>(h1);
        *reinterpret_cast<uint2*>(&g_hat[((size_t)b * NI + i) * (NJ * DJ) + 4 * t]) = st;
    }
}

// ============================================================================
// Routing pass. 128-thread blocks (4 warps), grid (64 b, 16) = 1024 blocks,
// all resident in ONE wave at occ 7 (128*7 = 896 thr/SM). warp = 16 i's,
// lane = output capsule j. Registers kept ~65: acc as 16 packed f32x2, hat
// kept as raw half2 in the load regs and converted twice (logit + acc).
// HAS_LOGIT=0: uniform c = 1/32 (iteration 0).
// HAS_LOGIT=1: c = softmax_j dot(op[j,:], hat[j,:]); op = g_outprev.
//   (pass 2 reuses this with op = out0+out1, since b2 = dot(out0+out1, hat))
// ============================================================================
template <int HAS_LOGIT>
__global__ __launch_bounds__(128, 7) void k_pass() {
    const int b    = blockIdx.x;
    const int warp = threadIdx.x >> 5;
    const int j    = threadIdx.x & 31;
    const int i0   = blockIdx.y * (PASS_WARPS * IPW) + warp * IPW;

    __shared__ __align__(16) float2 s_op2[16][NJ];   // [m-pair][j]
    if (HAS_LOGIT) {
        const int t = threadIdx.x;
        const float4* o4 = reinterpret_cast<const float4*>(&g_outprev[b * NJ * DJ]);
#pragma unroll
        for (int r = 0; r < 2; r++) {
            const int idx = t + r * 128;
            float4 f = o4[idx];
            const int jj = idx >> 3;
            const int mp = ((4 * idx) & 31) >> 1;   // m-pair index
            s_op2[mp + 0][jj] = make_float2(f.x, f.y);
            s_op2[mp + 1][jj] = make_float2(f.z, f.w);
        }
        __syncthreads();
    }

    unsigned long long a[16];
#pragma unroll
    for (int k = 0; k < 16; k++) a[k] = 0ULL;

    const uint4* p = reinterpret_cast<const uint4*>(
                         g_hat + ((size_t)b * NI + i0) * (NJ * DJ)) + j * 4;

    for (int it = 0; it < IPW; it++) {
        const uint4* pi = p + (size_t)it * 128;   // 128 uint4 = 2048 B = one i
        uint4 q0 = pi[0], q1 = pi[1], q2 = pi[2], q3 = pi[3];
        uint32_t h2[16] = {q0.x, q0.y, q0.z, q0.w, q1.x, q1.y, q1.z, q1.w,
                           q2.x, q2.y, q2.z, q2.w, q3.x, q3.y, q3.z, q3.w};

        float c;
        if (HAS_LOGIT) {
            unsigned long long l2 = 0ULL;
#pragma unroll
            for (int k = 0; k < 16; k++) {
                float2 f = h2f2(h2[k]);
                unsigned long long op =
                    *reinterpret_cast<const unsigned long long*>(&s_op2[k][j]);
                l2 = ffma2(op, pack2f(f.x, f.y), l2);
            }
            float2 lf = unpack2f(l2);
            float e = __expf(lf.x + lf.y);   // logits bounded; no max-sub needed
            float s = e;
#pragma unroll
            for (int o = 16; o > 0; o >>= 1)
                s += __shfl_xor_sync(0xffffffffu, s, o);
            c = e / s;
        } else {
            c = 1.0f / 32.0f;
        }

        const unsigned long long cc = pack2f(c, c);
#pragma unroll
        for (int k = 0; k < 16; k++) {
            float2 f = h2f2(h2[k]);
            a[k] = ffma2(cc, pack2f(f.x, f.y), a[k]);
        }
    }

    float* ap = &g_acc[(b * NJ + j) * DJ];
#pragma unroll
    for (int k = 0; k < 16; k++) {
        float2 v = unpack2f(a[k]);
        atomicAdd(ap + 2 * k + 0, v.x);
        atomicAdd(ap + 2 * k + 1, v.y);
    }
}

// ============================================================================
// Squash + re-zero g_acc. grid = BB, 1024 threads; warp = j, lane = m.
// MODE 0: g_outprev  = squash(acc)          (after pass 0 -> out0)
// MODE 1: g_outprev += squash(acc)          (after pass 1 -> out0+out1)
// MODE 2: out        = squash(acc)          (final)
// ============================================================================
template <int MODE>
__global__ void k_squash(float* __restrict__ out) {
    const int b = blockIdx.x;
    const int j = threadIdx.x >> 5;
    const int m = threadIdx.x & 31;
    const int idx = (b * NJ + j) * DJ + m;
    float s = g_acc[idx];
    g_acc[idx] = 0.f;
    float sq = s * s;
#pragma unroll
    for (int o = 16; o > 0; o >>= 1)
        sq += __shfl_xor_sync(0xffffffffu, sq, o);
    float scale = sq / ((1.f + sq) * sqrtf(sq + 1e-7f));
    float r = scale * s;
    if (MODE == 0)      g_outprev[idx] = r;
    else if (MODE == 1) g_outprev[idx] += r;
    else                out[idx] = r;
}

// ============================================================================
extern "C" void kernel_launch(void* const* d_in, const int* in_sizes, int n_in,
                              void* d_out, int out_size) {
    const float* inp = (const float*)d_in[0];  // [64, 1024, 16]
    const float* W   = (const float*)d_in[1];  // [1024, 32, 16, 32]
    float* out = (float*)d_out;                // [64, 32, 32]

    const dim3 passGrid(BB, PASS_GRID_Y);

    k_hat<<<NI, 256>>>(inp, W);

    k_pass<0><<<passGrid, 128>>>();
    k_squash<0><<<BB, 1024>>>(nullptr);

    k_pass<1><<<passGrid, 128>>>();
    k_squash<1><<<BB, 1024>>>(nullptr);

    k_pass<1><<<passGrid, 128>>>();   // b2 = dot(out0+out1, hat): same kernel
    k_squash<2><<<BB, 1024>>>(out);
}

// round 6
// speedup vs baseline: 1.3626x; 1.3626x over previous
#include <cuda_runtime.h>
#include <cuda_fp16.h>
#include <cstdint>
#include <cstddef>

// Problem dims
#define BB 64
#define NI 1024
#define DI 16
#define NJ 32
#define DJ 32
#define IPW 32                      // i's per block in routing passes
#define PASS_GRID_Y (NI / IPW)      // 32

// Scratch (device globals; no dynamic allocation allowed)
__device__ __align__(16) __half g_hat[(size_t)BB * NI * NJ * DJ];  // 128 MB
__device__ __align__(16) float  g_acc[BB * NJ * DJ];               // pre-squash accumulator
__device__ __align__(16) float  g_outprev[BB * NJ * DJ];           // logit operand (out0, then out0+out1)

// ---------- packed f32x2 helpers ----------
__device__ __forceinline__ unsigned long long pack2f(float x, float y) {
    unsigned long long r;
    asm("mov.b64 %0, {%1, %2};" : "=l"(r) : "f"(x), "f"(y));
    return r;
}
__device__ __forceinline__ unsigned long long ffma2(unsigned long long a, unsigned long long b,
                                                    unsigned long long c) {
    unsigned long long d;
    asm("fma.rn.f32x2 %0, %1, %2, %3;" : "=l"(d) : "l"(a), "l"(b), "l"(c));
    return d;
}
__device__ __forceinline__ float2 unpack2f(unsigned long long v) {
    float lo, hi;
    asm("mov.b64 {%0, %1}, %2;" : "=f"(lo), "=f"(hi) : "l"(v));
    return make_float2(lo, hi);
}
__device__ __forceinline__ float2 h2f2(uint32_t u) {
    __half2 h = *reinterpret_cast<__half2*>(&u);
    return __half22float2(h);
}

// ============================================================================
// K1: hat[b,i,j,m] = sum_n W[i,j,n,m] * x[b,i,n], stored fp16.
// grid = NI blocks (one i each), 256 threads; thread t owns jm = 4t..4t+3.
// Blocks 0..255 also zero g_acc so pass<0> starts clean.
// ============================================================================
__global__ __launch_bounds__(256) void k_hat(const float* __restrict__ inp,
                                             const float* __restrict__ W) {
    const int i = blockIdx.x;
    const int t = threadIdx.x;

    if (i < 256) g_acc[i * 256 + t] = 0.f;   // 256*256 = 65536 = BB*NJ*DJ

    const int j  = t >> 3;
    const int m0 = (4 * t) & 31;

    const float4* Wp = reinterpret_cast<const float4*>(
        W + ((size_t)i * NJ + j) * (DI * DJ) + m0);
    unsigned long long w01[16], w23[16];
#pragma unroll
    for (int n = 0; n < 16; n++) {
        float4 w = Wp[n * (DJ / 4)];
        w01[n] = pack2f(w.x, w.y);
        w23[n] = pack2f(w.z, w.w);
    }

    // Splatted x table: s_x2[b][n] = (x, x) as a 64-bit value.
    __shared__ __align__(16) float2 s_x2[BB][DI];
    {
        const int b  = t >> 2;               // 0..63
        const int q  = t & 3;                // 0..3 -> n = 4q..4q+3
        float4 v = reinterpret_cast<const float4*>(inp)[((size_t)b * NI + i) * 4 + q];
        s_x2[b][4 * q + 0] = make_float2(v.x, v.x);
        s_x2[b][4 * q + 1] = make_float2(v.y, v.y);
        s_x2[b][4 * q + 2] = make_float2(v.z, v.z);
        s_x2[b][4 * q + 3] = make_float2(v.w, v.w);
    }
    __syncthreads();

#pragma unroll 2
    for (int b = 0; b < BB; b++) {
        unsigned long long a01 = 0ULL, a23 = 0ULL;
#pragma unroll
        for (int n = 0; n < 16; n++) {
            unsigned long long xx =
                *reinterpret_cast<const unsigned long long*>(&s_x2[b][n]);
            a01 = ffma2(xx, w01[n], a01);
            a23 = ffma2(xx, w23[n], a23);
        }
        float2 f01 = unpack2f(a01);
        float2 f23 = unpack2f(a23);
        __half2 h0 = __floats2half2_rn(f01.x, f01.y);
        __half2 h1 = __floats2half2_rn(f23.x, f23.y);
        uint2 st;
        st.x = reinterpret_cast<uint32_t&>(h0);
        st.y = reinterpret_cast<uint32_t&>(h1);
        *reinterpret_cast<uint2*>(&g_hat[((size_t)b * NI + i) * (NJ * DJ) + 4 * t]) = st;
    }
}

// ============================================================================
// Routing pass, block-cooperative layout for perfectly coalesced hat loads.
// 128-thread block (4 warps) processes one i per step, IPW i's total:
//   warp w, lane l loads uint4 (w*32 + l) of the 2048-byte row -> each warp's
//   LDG.128 covers 512 consecutive bytes (4 lines, minimal L1 wavefronts).
//   Lane l owns j = w*8 + l/4 and m = 8*(l&3)..+8 (8 halves).
// Logit: 8-wide packed dot + shfl over the 4-lane m-group; op slice (8 floats)
// hoisted into registers before the loop. Softmax denominator crosses warps
// via a parity-double-buffered 4-float smem slot + ONE __syncthreads per i.
// grid = (BB, NI/IPW) = 2048 blocks -> single wave at >=14 blocks/SM.
// ============================================================================
template <int HAS_LOGIT>
__global__ __launch_bounds__(128) void k_pass() {
    const int b = blockIdx.x;
    const int w = threadIdx.x >> 5;
    const int l = threadIdx.x & 31;
    const int u = l & 3;
    const int j = w * 8 + (l >> 2);
    const int i0 = blockIdx.y * IPW;

    unsigned long long op2[4];
    if (HAS_LOGIT) {
        const float4* o4 = reinterpret_cast<const float4*>(
            &g_outprev[(b * NJ + j) * DJ + 8 * u]);
        float4 f0 = o4[0], f1 = o4[1];
        op2[0] = pack2f(f0.x, f0.y);
        op2[1] = pack2f(f0.z, f0.w);
        op2[2] = pack2f(f1.x, f1.y);
        op2[3] = pack2f(f1.z, f1.w);
    }

    __shared__ float s_red[2][4];

    unsigned long long a0 = 0ULL, a1 = 0ULL, a2 = 0ULL, a3 = 0ULL;

    const uint4* p = reinterpret_cast<const uint4*>(
                         g_hat + ((size_t)b * NI + i0) * (NJ * DJ)) + (w * 32 + l);

    uint4 cur = p[0];
    for (int it = 0; it < IPW; it++) {
        const int nx = (it + 1 < IPW) ? (it + 1) : it;
        uint4 nxt = p[(size_t)nx * 128];

        float2 f0 = h2f2(cur.x), f1 = h2f2(cur.y), f2 = h2f2(cur.z), f3 = h2f2(cur.w);
        unsigned long long hf0 = pack2f(f0.x, f0.y);
        unsigned long long hf1 = pack2f(f1.x, f1.y);
        unsigned long long hf2 = pack2f(f2.x, f2.y);
        unsigned long long hf3 = pack2f(f3.x, f3.y);

        float c;
        if (HAS_LOGIT) {
            unsigned long long l2 = 0ULL;
            l2 = ffma2(op2[0], hf0, l2);
            l2 = ffma2(op2[1], hf1, l2);
            l2 = ffma2(op2[2], hf2, l2);
            l2 = ffma2(op2[3], hf3, l2);
            float2 lf = unpack2f(l2);
            float logit = lf.x + lf.y;
            logit += __shfl_xor_sync(0xffffffffu, logit, 1);
            logit += __shfl_xor_sync(0xffffffffu, logit, 2);
            float e = __expf(logit);           // logits bounded; no max-sub needed
            float se = e;
            se += __shfl_xor_sync(0xffffffffu, se, 4);
            se += __shfl_xor_sync(0xffffffffu, se, 8);
            se += __shfl_xor_sync(0xffffffffu, se, 16);   // = 4 * sum_{j in warp} e_j
            if (l == 0) s_red[it & 1][w] = se;
            __syncthreads();
            float tot = s_red[it & 1][0] + s_red[it & 1][1] +
                        s_red[it & 1][2] + s_red[it & 1][3];
            c = 4.f * e / tot;                 // tot = 4 * sum_all e_j
        } else {
            c = 1.0f / 32.0f;
        }

        const unsigned long long cc = pack2f(c, c);
        a0 = ffma2(cc, hf0, a0);
        a1 = ffma2(cc, hf1, a1);
        a2 = ffma2(cc, hf2, a2);
        a3 = ffma2(cc, hf3, a3);

        cur = nxt;
    }

    float* ap = &g_acc[(b * NJ + j) * DJ + 8 * u];
    float2 v;
    v = unpack2f(a0); atomicAdd(ap + 0, v.x); atomicAdd(ap + 1, v.y);
    v = unpack2f(a1); atomicAdd(ap + 2, v.x); atomicAdd(ap + 3, v.y);
    v = unpack2f(a2); atomicAdd(ap + 4, v.x); atomicAdd(ap + 5, v.y);
    v = unpack2f(a3); atomicAdd(ap + 6, v.x); atomicAdd(ap + 7, v.y);
}

// ============================================================================
// Squash + re-zero g_acc. grid = BB, 1024 threads; warp = j, lane = m.
// MODE 0: g_outprev  = squash(acc)   (after pass 0 -> out0)
// MODE 1: g_outprev += squash(acc)   (after pass 1 -> out0+out1; b2 identity)
// MODE 2: out        = squash(acc)   (final)
// ============================================================================
template <int MODE>
__global__ void k_squash(float* __restrict__ out) {
    const int b = blockIdx.x;
    const int j = threadIdx.x >> 5;
    const int m = threadIdx.x & 31;
    const int idx = (b * NJ + j) * DJ + m;
    float s = g_acc[idx];
    g_acc[idx] = 0.f;
    float sq = s * s;
#pragma unroll
    for (int o = 16; o > 0; o >>= 1)
        sq += __shfl_xor_sync(0xffffffffu, sq, o);
    float scale = sq / ((1.f + sq) * sqrtf(sq + 1e-7f));
    float r = scale * s;
    if (MODE == 0)      g_outprev[idx] = r;
    else if (MODE == 1) g_outprev[idx] += r;
    else                out[idx] = r;
}

// ============================================================================
extern "C" void kernel_launch(void* const* d_in, const int* in_sizes, int n_in,
                              void* d_out, int out_size) {
    const float* inp = (const float*)d_in[0];  // [64, 1024, 16]
    const float* W   = (const float*)d_in[1];  // [1024, 32, 16, 32]
    float* out = (float*)d_out;                // [64, 32, 32]

    const dim3 passGrid(BB, PASS_GRID_Y);

    k_hat<<<NI, 256>>>(inp, W);

    k_pass<0><<<passGrid, 128>>>();
    k_squash<0><<<BB, 1024>>>(nullptr);

    k_pass<1><<<passGrid, 128>>>();
    k_squash<1><<<BB, 1024>>>(nullptr);

    k_pass<1><<<passGrid, 128>>>();   // b2 = dot(out0+out1, hat): same kernel
    k_squash<2><<<BB, 1024>>>(out);
}

// round 8
// speedup vs baseline: 1.5699x; 1.1521x over previous
#include <cuda_runtime.h>
#include <cuda_fp16.h>
#include <cstdint>
#include <cstddef>

// Problem dims
#define BB 64
#define NI 1024
#define DI 16
#define NJ 32
#define DJ 32
#define IPW 32                      // i's per block in routing passes
#define PASS_GRID_Y (NI / IPW)      // 32

// Scratch (device globals; no dynamic allocation allowed)
__device__ __align__(16) __half g_hat[(size_t)BB * NI * NJ * DJ];  // 128 MB
__device__ __align__(16) float  g_acc[3][BB * NJ * DJ];            // per-iteration accumulators

// ---------- packed f32x2 helpers ----------
__device__ __forceinline__ unsigned long long pack2f(float x, float y) {
    unsigned long long r;
    asm("mov.b64 %0, {%1, %2};" : "=l"(r) : "f"(x), "f"(y));
    return r;
}
__device__ __forceinline__ unsigned long long ffma2(unsigned long long a, unsigned long long b,
                                                    unsigned long long c) {
    unsigned long long d;
    asm("fma.rn.f32x2 %0, %1, %2, %3;" : "=l"(d) : "l"(a), "l"(b), "l"(c));
    return d;
}
__device__ __forceinline__ float2 unpack2f(unsigned long long v) {
    float lo, hi;
    asm("mov.b64 {%0, %1}, %2;" : "=f"(lo), "=f"(hi) : "l"(v));
    return make_float2(lo, hi);
}
__device__ __forceinline__ float2 h2f2(uint32_t u) {
    __half2 h = *reinterpret_cast<__half2*>(&u);
    return __half22float2(h);
}

// ============================================================================
// K1: hat[b,i,j,m] = sum_n W[i,j,n,m] * x[b,i,n], stored fp16.
// grid = NI blocks (one i each), 256 threads; thread t owns jm = 4t..4t+3.
// Blocks 0..767 zero the three acc buffers (768*256 = 3*65536).
// ============================================================================
__global__ __launch_bounds__(256) void k_hat(const float* __restrict__ inp,
                                             const float* __restrict__ W) {
    const int i = blockIdx.x;
    const int t = threadIdx.x;

    if (i < 768) (&g_acc[0][0])[i * 256 + t] = 0.f;

    const int j  = t >> 3;
    const int m0 = (4 * t) & 31;

    const float4* Wp = reinterpret_cast<const float4*>(
        W + ((size_t)i * NJ + j) * (DI * DJ) + m0);
    unsigned long long w01[16], w23[16];
#pragma unroll
    for (int n = 0; n < 16; n++) {
        float4 w = Wp[n * (DJ / 4)];
        w01[n] = pack2f(w.x, w.y);
        w23[n] = pack2f(w.z, w.w);
    }

    // Splatted x table: s_x2[b][n] = (x, x) as a 64-bit value.
    __shared__ __align__(16) float2 s_x2[BB][DI];
    {
        const int b  = t >> 2;               // 0..63
        const int q  = t & 3;                // 0..3 -> n = 4q..4q+3
        float4 v = reinterpret_cast<const float4*>(inp)[((size_t)b * NI + i) * 4 + q];
        s_x2[b][4 * q + 0] = make_float2(v.x, v.x);
        s_x2[b][4 * q + 1] = make_float2(v.y, v.y);
        s_x2[b][4 * q + 2] = make_float2(v.z, v.z);
        s_x2[b][4 * q + 3] = make_float2(v.w, v.w);
    }
    __syncthreads();

#pragma unroll 2
    for (int b = 0; b < BB; b++) {
        unsigned long long a01 = 0ULL, a23 = 0ULL;
#pragma unroll
        for (int n = 0; n < 16; n++) {
            unsigned long long xx =
                *reinterpret_cast<const unsigned long long*>(&s_x2[b][n]);
            a01 = ffma2(xx, w01[n], a01);
            a23 = ffma2(xx, w23[n], a23);
        }
        float2 f01 = unpack2f(a01);
        float2 f23 = unpack2f(a23);
        __half2 h0 = __floats2half2_rn(f01.x, f01.y);
        __half2 h1 = __floats2half2_rn(f23.x, f23.y);
        uint2 st;
        st.x = reinterpret_cast<uint32_t&>(h0);
        st.y = reinterpret_cast<uint32_t&>(h1);
        *reinterpret_cast<uint2*>(&g_hat[((size_t)b * NI + i) * (NJ * DJ) + 4 * t]) = st;
    }
}

// ============================================================================
// Redundant per-block squash of one acc buffer -> this thread's 8-float op
// slice (j = its j, m = 8u..8u+8). 4-lane shuffle reduction, no smem/barrier.
// ============================================================================
__device__ __forceinline__ void load_op_squash(const float* __restrict__ acc,
                                               int b, int j, int u, float op[8]) {
    const float4* a4 = reinterpret_cast<const float4*>(&acc[(b * NJ + j) * DJ + 8 * u]);
    float4 f0 = a4[0], f1 = a4[1];
    op[0] = f0.x; op[1] = f0.y; op[2] = f0.z; op[3] = f0.w;
    op[4] = f1.x; op[5] = f1.y; op[6] = f1.z; op[7] = f1.w;
    float sq = 0.f;
#pragma unroll
    for (int k = 0; k < 8; k++) sq = fmaf(op[k], op[k], sq);
    sq += __shfl_xor_sync(0xffffffffu, sq, 1);
    sq += __shfl_xor_sync(0xffffffffu, sq, 2);   // full ||s_j||^2 (32 m's)
    float scale = sq / ((1.f + sq) * sqrtf(sq + 1e-7f));
#pragma unroll
    for (int k = 0; k < 8; k++) op[k] *= scale;
}

// ============================================================================
// Routing pass, block-cooperative coalesced layout + depth-3 rolling prefetch.
// 128-thread block (4 warps) processes one i per step; warp w lane l loads
// uint4 (w*32+l) of the 2048-byte row (perfectly coalesced). Lane owns
// j = w*8 + l/4, m = 8(l&3)..+8.
// PHASE 0: c = 1/32 uniform,                     writes g_acc[0]
// PHASE 1: op = squash(acc0),                    writes g_acc[1]
// PHASE 2: op = squash(acc0)+squash(acc1),       writes g_acc[2]
// Softmax denominator crosses warps via parity-double-buffered smem + 1 BAR/i.
// ============================================================================
template <int PHASE>
__global__ __launch_bounds__(128) void k_pass() {
    const int b = blockIdx.x;
    const int w = threadIdx.x >> 5;
    const int l = threadIdx.x & 31;
    const int u = l & 3;
    const int j = w * 8 + (l >> 2);
    const int i0 = blockIdx.y * IPW;

    unsigned long long op2[4];
    if (PHASE >= 1) {
        float op[8];
        load_op_squash(g_acc[0], b, j, u, op);
        if (PHASE == 2) {
            float op1[8];
            load_op_squash(g_acc[1], b, j, u, op1);
#pragma unroll
            for (int k = 0; k < 8; k++) op[k] += op1[k];
        }
        op2[0] = pack2f(op[0], op[1]);
        op2[1] = pack2f(op[2], op[3]);
        op2[2] = pack2f(op[4], op[5]);
        op2[3] = pack2f(op[6], op[7]);
    }

    __shared__ float s_red[2][4];

    unsigned long long a0 = 0ULL, a1 = 0ULL, a2 = 0ULL, a3 = 0ULL;

    const uint4* p = reinterpret_cast<const uint4*>(
                         g_hat + ((size_t)b * NI + i0) * (NJ * DJ)) + (w * 32 + l);

    uint4 buf[4];
    buf[0] = p[0];
    buf[1] = p[128];
    buf[2] = p[256];

#pragma unroll 4
    for (int it = 0; it < IPW; it++) {
        const int pf = (it + 3 < IPW) ? (it + 3) : (IPW - 1);
        buf[(it + 3) & 3] = p[(size_t)pf * 128];
        uint4 cur = buf[it & 3];

        float2 f0 = h2f2(cur.x), f1 = h2f2(cur.y), f2 = h2f2(cur.z), f3 = h2f2(cur.w);
        unsigned long long hf0 = pack2f(f0.x, f0.y);
        unsigned long long hf1 = pack2f(f1.x, f1.y);
        unsigned long long hf2 = pack2f(f2.x, f2.y);
        unsigned long long hf3 = pack2f(f3.x, f3.y);

        float c;
        if (PHASE >= 1) {
            unsigned long long l2 = 0ULL;
            l2 = ffma2(op2[0], hf0, l2);
            l2 = ffma2(op2[1], hf1, l2);
            l2 = ffma2(op2[2], hf2, l2);
            l2 = ffma2(op2[3], hf3, l2);
            float2 lf = unpack2f(l2);
            float logit = lf.x + lf.y;
            logit += __shfl_xor_sync(0xffffffffu, logit, 1);
            logit += __shfl_xor_sync(0xffffffffu, logit, 2);
            float e = __expf(logit);           // logits bounded; no max-sub needed
            float se = e;
            se += __shfl_xor_sync(0xffffffffu, se, 4);
            se += __shfl_xor_sync(0xffffffffu, se, 8);
            se += __shfl_xor_sync(0xffffffffu, se, 16);   // = 4 * sum_{j in warp} e_j
            if (l == 0) s_red[it & 1][w] = se;
            __syncthreads();
            float tot = s_red[it & 1][0] + s_red[it & 1][1] +
                        s_red[it & 1][2] + s_red[it & 1][3];
            c = 4.f * e / tot;                 // tot = 4 * sum_all e_j
        } else {
            c = 1.0f / 32.0f;
        }

        const unsigned long long cc = pack2f(c, c);
        a0 = ffma2(cc, hf0, a0);
        a1 = ffma2(cc, hf1, a1);
        a2 = ffma2(cc, hf2, a2);
        a3 = ffma2(cc, hf3, a3);
    }

    float* ap = &g_acc[PHASE][(b * NJ + j) * DJ + 8 * u];
    float2 v;
    v = unpack2f(a0); atomicAdd(ap + 0, v.x); atomicAdd(ap + 1, v.y);
    v = unpack2f(a1); atomicAdd(ap + 2, v.x); atomicAdd(ap + 3, v.y);
    v = unpack2f(a2); atomicAdd(ap + 4, v.x); atomicAdd(ap + 5, v.y);
    v = unpack2f(a3); atomicAdd(ap + 6, v.x); atomicAdd(ap + 7, v.y);
}

// ============================================================================
// Final squash: out = squash(g_acc[2]). grid = BB, 1024 threads; warp=j, lane=m.
// ============================================================================
__global__ void k_squash_final(float* __restrict__ out) {
    const int b = blockIdx.x;
    const int j = threadIdx.x >> 5;
    const int m = threadIdx.x & 31;
    const int idx = (b * NJ + j) * DJ + m;
    float s = g_acc[2][idx];
    float sq = s * s;
#pragma unroll
    for (int o = 16; o > 0; o >>= 1)
        sq += __shfl_xor_sync(0xffffffffu, sq, o);
    float scale = sq / ((1.f + sq) * sqrtf(sq + 1e-7f));
    out[idx] = scale * s;
}

// ============================================================================
extern "C" void kernel_launch(void* const* d_in, const int* in_sizes, int n_in,
                              void* d_out, int out_size) {
    const float* inp = (const float*)d_in[0];  // [64, 1024, 16]
    const float* W   = (const float*)d_in[1];  // [1024, 32, 16, 32]
    float* out = (float*)d_out;                // [64, 32, 32]

    const dim3 passGrid(BB, PASS_GRID_Y);

    k_hat<<<NI, 256>>>(inp, W);

    k_pass<0><<<passGrid, 128>>>();
    k_pass<1><<<passGrid, 128>>>();
    k_pass<2><<<passGrid, 128>>>();

    k_squash_final<<<BB, 1024>>>(out);
}